// round 13
// baseline (speedup 1.0000x reference)
#include <cuda_runtime.h>
#include <math.h>

#define NPTS 16384
#define KNN 8
#define GDIM 32
#define NCELL (GDIM * GDIM * GDIM)   // 32768
#define GLO (-5.0f)
#define GSPAN 10.0f
#define LPQ 8             // lanes per query
#define QTPB 256
#define QPB (QTPB / LPQ)  // 32 queries per block

// ---------------- scratch (static device globals; no allocation) ----------------
// NOTE: g_cnt/g_fill start zero (static init) and are re-zeroed by knn_scan_kernel
// after use -> every kernel_launch call sees them zeroed (replay-deterministic).
__device__ __align__(16) float4 g_ppos[NPTS];   // cell-sorted: x,y,z, w=sq
__device__ int   g_pid[NPTS];                   // cell-sorted original ids
__device__ int   g_cellof[NPTS];
__device__ int   g_cnt[NCELL];
__device__ int   g_fill[NCELL];
__device__ int   g_start[NCELL + 1];
__device__ int   g_idx[NPTS * KNN];
__device__ float g_P1[NPTS * 32];
__device__ float g_S1[NPTS * 32];
__device__ float g_x1[NPTS * 64];
__device__ float g_P2[NPTS * 64];
__device__ float g_S2[NPTS * 64];
__device__ float g_x2[NPTS * 128];

typedef unsigned long long u64;

// ---------------- f32x2 packed helpers (sm_100+: fma.rn.f32x2) ----------------
__device__ __forceinline__ u64 splat_f32x2(float v) {
  u64 r;
  asm("mov.b64 %0, {%1, %1};" : "=l"(r) : "f"(v));
  return r;
}
__device__ __forceinline__ u64 fma_f32x2(u64 a, u64 b, u64 c) {
  u64 d;
  asm("fma.rn.f32x2 %0, %1, %2, %3;" : "=l"(d) : "l"(a), "l"(b), "l"(c));
  return d;
}
__device__ __forceinline__ void unpack_f32x2(u64 v, float& lo, float& hi) {
  asm("mov.b64 {%0, %1}, %2;" : "=f"(lo), "=f"(hi) : "l"(v));
}

// Sorted top-8 insertion, static indices only (stays in registers).
__device__ __forceinline__ void insert8(float d, int jj, float bd[KNN], int bi[KNN]) {
#pragma unroll
  for (int s = KNN - 1; s >= 1; s--) {
    bool shift = (d < bd[s - 1]);
    bd[s] = shift ? bd[s - 1] : d;
    bi[s] = shift ? bi[s - 1] : jj;
    if (!shift) return;
  }
  bd[0] = d; bi[0] = jj;
}

__device__ __forceinline__ int cell_coord(float v) {
  const float inv = (float)GDIM / GSPAN;
  int c = (int)floorf((v - GLO) * inv);
  return min(GDIM - 1, max(0, c));
}

// ---------------- grid build ----------------
__global__ void knn_hist_kernel(const float* __restrict__ pos) {
  const int i = blockIdx.x * 256 + threadIdx.x;
  const float x = pos[3 * i], y = pos[3 * i + 1], z = pos[3 * i + 2];
  const int c = (cell_coord(z) * GDIM + cell_coord(y)) * GDIM + cell_coord(x);
  g_cellof[i] = c;
  atomicAdd(&g_cnt[c], 1);
}

// single-block scan over 32768 cells; consumes+resets g_cnt and g_fill
__global__ void __launch_bounds__(1024) knn_scan_kernel() {
  __shared__ int part[1024];
  const int t = threadIdx.x;
  const int base = t * (NCELL / 1024);  // 32 cells per thread
  int loc[NCELL / 1024];
  int s = 0;
#pragma unroll
  for (int k = 0; k < NCELL / 1024; k++) { loc[k] = s; s += g_cnt[base + k]; }
  part[t] = s;
  __syncthreads();
  for (int off = 1; off < 1024; off <<= 1) {
    int v = (t >= off) ? part[t - off] : 0;
    __syncthreads();
    part[t] += v;
    __syncthreads();
  }
  const int excl = part[t] - s;
#pragma unroll
  for (int k = 0; k < NCELL / 1024; k++) {
    g_start[base + k] = excl + loc[k];
    g_cnt[base + k] = 0;    // reset for next replay
    g_fill[base + k] = 0;   // reset for scatter
  }
  if (t == 1023) g_start[NCELL] = NPTS;
}

__global__ void knn_scatter_kernel(const float* __restrict__ pos) {
  const int i = blockIdx.x * 256 + threadIdx.x;
  const int c = g_cellof[i];
  const int slot = g_start[c] + atomicAdd(&g_fill[c], 1);
  const float x = pos[3 * i], y = pos[3 * i + 1], z = pos[3 * i + 2];
  const float sq = fmaf(x, x, fmaf(y, y, z * z));
  g_ppos[slot] = make_float4(x, y, z, sq);
  g_pid[slot] = i;
}

// -------- exact grid kNN: 8 lanes/query, row ranges, certified-threshold pruning,
//          shfl extraction merge --------
__global__ void __launch_bounds__(QTPB) knn_query_kernel() {
  const int t = threadIdx.x;
  const int l8 = t & (LPQ - 1);
  const int g = t >> 3;
  const int s = blockIdx.x * QPB + g;           // sorted slot of this query
  const int wl = t & 31;
  const unsigned gmask = 0xFFu << (wl & ~7);    // the 8 lanes of my group

  const float4 me = g_ppos[s];
  const float sqi = me.w;
  const int cx = cell_coord(me.x);
  const int cy = cell_coord(me.y);
  const int cz = cell_coord(me.z);

  float bd[KNN]; int bi[KNN];
#pragma unroll
  for (int k = 0; k < KNN; k++) { bd[k] = 3.0e38f; bi[k] = -1; }
  float worst = 3.0e38f;
  // Certified union-8th upper bound: the 8 lanes' bd[0] are 8 distinct retained
  // elements, so union-8th <= max over lanes of bd[0]. Candidates with d > T are
  // provably outside the union top-8 (8 strictly smaller retained elements exist,
  // and that count is monotone under evictions) -> safe to skip insertion.
  float T = 3.0e38f;
  const float h = GSPAN / (float)GDIM;

  // lanes stride a contiguous slot range [lo, hi); refresh T after each range
  auto scan_range = [&](int lo, int hi) {
    for (int q = lo + l8; q < hi; q += LPQ) {
      const float4 p = __ldg(&g_ppos[q]);
      const float td = fmaf(me.x, p.x, fmaf(me.y, p.y, me.z * p.z));
      const float d = fmaf(-2.0f, td, sqi + p.w);  // same formula as reference
      if (d <= T && d < worst && q != s) {         // self-exclusion by slot
        insert8(d, q, bd, bi);
        worst = bd[KNN - 1];
      }
    }
    float m = bd[0];
    m = fmaxf(m, __shfl_xor_sync(gmask, m, 1, LPQ));
    m = fmaxf(m, __shfl_xor_sync(gmask, m, 2, LPQ));
    m = fmaxf(m, __shfl_xor_sync(gmask, m, 4, LPQ));
    T = m;
  };

  for (int r = 1; r < GDIM; r++) {
    const int x0 = max(cx - r, 0), x1 = min(cx + r, GDIM - 1);
    const int y0 = max(cy - r, 0), y1 = min(cy + r, GDIM - 1);
    const int z0 = max(cz - r, 0), z1 = min(cz + r, GDIM - 1);
    if (r == 1) {
      // full 3x3x3 box (r=0 and r=1 together) as contiguous full rows
      for (int z = z0; z <= z1; z++)
        for (int y = y0; y <= y1; y++) {
          const int rb = (z * GDIM + y) * GDIM;
          scan_range(__ldg(&g_start[rb + x0]), __ldg(&g_start[rb + x1 + 1]));
        }
    } else {
      // shell at radius r (box r-1 fully scanned)
      for (int z = z0; z <= z1; z++) {
        const int rz = abs(z - cz);
        for (int y = y0; y <= y1; y++) {
          const int ry = max(rz, abs(y - cy));
          const int rb = (z * GDIM + y) * GDIM;
          if (ry == r) {
            scan_range(__ldg(&g_start[rb + x0]), __ldg(&g_start[rb + x1 + 1]));
          } else {
            if (cx - r >= 0)
              scan_range(__ldg(&g_start[rb + cx - r]), __ldg(&g_start[rb + cx - r + 1]));
            if (cx + r < GDIM)
              scan_range(__ldg(&g_start[rb + cx + r]), __ldg(&g_start[rb + cx + r + 1]));
          }
        }
      }
    }
    // exact min distance from query to unscanned region (clamp-safe):
    // covered/clamped faces contribute 1e18 (so g2<=1e36 < 3e38 sentinel).
    float bnd = 1e18f;
    if (cx - r > 0)         bnd = fminf(bnd, me.x - (GLO + (float)(cx - r) * h));
    if (cx + r < GDIM - 1)  bnd = fminf(bnd, (GLO + (float)(cx + r + 1) * h) - me.x);
    if (cy - r > 0)         bnd = fminf(bnd, me.y - (GLO + (float)(cy - r) * h));
    if (cy + r < GDIM - 1)  bnd = fminf(bnd, (GLO + (float)(cy + r + 1) * h) - me.y);
    if (cz - r > 0)         bnd = fminf(bnd, me.z - (GLO + (float)(cz - r) * h));
    if (cz + r < GDIM - 1)  bnd = fminf(bnd, (GLO + (float)(cz + r + 1) * h) - me.z);
    const float g2 = bnd * bnd;
    int cnt = 0;
#pragma unroll
    for (int k = 0; k < KNN; k++) cnt += (bd[k] < g2) ? 1 : 0;
    cnt += __shfl_xor_sync(gmask, cnt, 1, LPQ);
    cnt += __shfl_xor_sync(gmask, cnt, 2, LPQ);
    cnt += __shfl_xor_sync(gmask, cnt, 4, LPQ);
    if (cnt >= KNN) break;  // union's 8th-smallest < g2 <= any unseen point
  }

  // extraction merge: 8 rounds of width-8 argmin over sorted per-lane lists.
  // Tie-break by lane index (matches previous lane-order smem merge). Winner
  // pops its head via constant-index register shift.
  int outslot = 0;
#pragma unroll
  for (int k = 0; k < KNN; k++) {
    float mv = bd[0]; int ml = l8; int mi = bi[0];
#pragma unroll
    for (int off = 1; off < LPQ; off <<= 1) {
      const float ov = __shfl_xor_sync(gmask, mv, off, LPQ);
      const int ol = __shfl_xor_sync(gmask, ml, off, LPQ);
      const int oi = __shfl_xor_sync(gmask, mi, off, LPQ);
      if (ov < mv || (ov == mv && ol < ml)) { mv = ov; ml = ol; mi = oi; }
    }
    if (l8 == k) outslot = mi;     // lane k owns the k-th nearest
    if (ml == l8) {                // winning lane pops its head
#pragma unroll
      for (int j = 0; j < KNN - 1; j++) { bd[j] = bd[j + 1]; bi[j] = bi[j + 1]; }
      bd[KNN - 1] = 3.0e38f; bi[KNN - 1] = -1;
    }
  }
  const int myid = __ldg(&g_pid[s]);
  g_idx[myid * KNN + l8] = __ldg(&g_pid[outslot]);  // slot -> original id
}

// ---------------- layer-1 factoring: P1[j] = pos_j@(Wtop+Wbot)+b1a, S1[i] = pos_i@Wbot
__global__ void pre1_kernel(const float* __restrict__ pos,
                            const float* __restrict__ W1a,
                            const float* __restrict__ b1a) {
  __shared__ float w[6 * 32];
  __shared__ float b[32];
  if (threadIdx.x < 192) w[threadIdx.x] = W1a[threadIdx.x];
  if (threadIdx.x < 32) b[threadIdx.x] = b1a[threadIdx.x];
  __syncthreads();
  const int t = blockIdx.x * blockDim.x + threadIdx.x;
  const int i = t >> 5, c = t & 31;
  const float x = pos[3 * i], y = pos[3 * i + 1], z = pos[3 * i + 2];
  const float cb = fmaf(x, w[96 + c], fmaf(y, w[128 + c], z * w[160 + c]));
  const float pa = fmaf(x, w[c], fmaf(y, w[32 + c], fmaf(z, w[64 + c], b[c])));
  g_P1[t] = pa + cb;
  g_S1[t] = cb;
}

// ---------------- layer-2 factoring ----------------
__global__ void pre2_kernel(const float* __restrict__ pos,
                            const float* __restrict__ W2a,
                            const float* __restrict__ b2a) {
  const int t = blockIdx.x * blockDim.x + threadIdx.x;
  const int i = t >> 6, c = t & 63;
  float acc = __ldg(&b2a[c]);
  const float* xr = &g_x1[i * 64];
#pragma unroll 8
  for (int k = 0; k < 64; k++) acc = fmaf(xr[k], __ldg(&W2a[k * 64 + c]), acc);
  const float x = pos[3 * i], y = pos[3 * i + 1], z = pos[3 * i + 2];
  const float r = fmaf(x, __ldg(&W2a[64 * 64 + c]),
                  fmaf(y, __ldg(&W2a[65 * 64 + c]), z * __ldg(&W2a[66 * 64 + c])));
  g_P2[t] = acc + r;
  g_S2[t] = r;
}

// ---------------- shared conv core: h = relu(P[j]-S[i]); out = relu(max_s(h@W2) + b2)
// inner GEMM on packed fma.rn.f32x2 (bit-identical per-channel fp32 chains)
template <int HD, int OD, int PTS, int NT>
__device__ __forceinline__ void conv_impl(const float* __restrict__ P,
                                          const float* __restrict__ S,
                                          const float* __restrict__ W2,
                                          const float* __restrict__ b2,
                                          float* __restrict__ out) {
  constexpr int HSTR = PTS + 4;
  constexpr int SSTR = HD + 4;
  constexpr int CHG = OD / 4;
  __shared__ __align__(16) float Hsm[HD * HSTR];
  __shared__ __align__(16) float Ssm[PTS * SSTR];
  __shared__ int Ism[PTS * KNN];
  const int t = threadIdx.x;
  const int pt_base = blockIdx.x * PTS;
  const int chg = t % CHG;
  const int ptg = t / CHG;
  {
    const int lin = t * 8;
    const int p = lin / HD, k = lin % HD;
    const float4 a = *(const float4*)&S[(pt_base + p) * HD + k];
    const float4 bq = *(const float4*)&S[(pt_base + p) * HD + k + 4];
    *(float4*)&Ssm[p * SSTR + k] = a;
    *(float4*)&Ssm[p * SSTR + k + 4] = bq;
  }
  for (int q = t; q < PTS * KNN; q += NT) Ism[q] = g_idx[pt_base * KNN + q];

  float4 acc0 = make_float4(-1e30f, -1e30f, -1e30f, -1e30f);
  float4 acc1 = acc0, acc2 = acc0, acc3 = acc0;

  const int fp = t % PTS;
  const int fk = (t / PTS) * 8;

  for (int s = 0; s <= KNN; s++) {
    __syncthreads();
    {
      const int j = (s < KNN) ? Ism[fp * KNN + s] : (pt_base + fp);
      const float4 a = *(const float4*)&P[j * HD + fk];
      const float4 bq = *(const float4*)&P[j * HD + fk + 4];
      const float4 sa = *(const float4*)&Ssm[fp * SSTR + fk];
      const float4 sb = *(const float4*)&Ssm[fp * SSTR + fk + 4];
      Hsm[(fk + 0) * HSTR + fp] = fmaxf(a.x - sa.x, 0.f);
      Hsm[(fk + 1) * HSTR + fp] = fmaxf(a.y - sa.y, 0.f);
      Hsm[(fk + 2) * HSTR + fp] = fmaxf(a.z - sa.z, 0.f);
      Hsm[(fk + 3) * HSTR + fp] = fmaxf(a.w - sa.w, 0.f);
      Hsm[(fk + 4) * HSTR + fp] = fmaxf(bq.x - sb.x, 0.f);
      Hsm[(fk + 5) * HSTR + fp] = fmaxf(bq.y - sb.y, 0.f);
      Hsm[(fk + 6) * HSTR + fp] = fmaxf(bq.z - sb.z, 0.f);
      Hsm[(fk + 7) * HSTR + fp] = fmaxf(bq.w - sb.w, 0.f);
    }
    __syncthreads();
    u64 o0a = 0, o0b = 0, o1a = 0, o1b = 0, o2a = 0, o2b = 0, o3a = 0, o3b = 0;
#pragma unroll 8
    for (int k = 0; k < HD; k++) {
      const float4 hv = *(const float4*)&Hsm[k * HSTR + ptg * 4];      // broadcast
      const ulonglong2 wv = __ldg((const ulonglong2*)&W2[k * OD + chg * 4]);
      const u64 hx = splat_f32x2(hv.x);
      const u64 hy = splat_f32x2(hv.y);
      const u64 hz = splat_f32x2(hv.z);
      const u64 hw = splat_f32x2(hv.w);
      o0a = fma_f32x2(hx, wv.x, o0a); o0b = fma_f32x2(hx, wv.y, o0b);
      o1a = fma_f32x2(hy, wv.x, o1a); o1b = fma_f32x2(hy, wv.y, o1b);
      o2a = fma_f32x2(hz, wv.x, o2a); o2b = fma_f32x2(hz, wv.y, o2b);
      o3a = fma_f32x2(hw, wv.x, o3a); o3b = fma_f32x2(hw, wv.y, o3b);
    }
    float lo, hi;
    unpack_f32x2(o0a, lo, hi); acc0.x = fmaxf(acc0.x, lo); acc0.y = fmaxf(acc0.y, hi);
    unpack_f32x2(o0b, lo, hi); acc0.z = fmaxf(acc0.z, lo); acc0.w = fmaxf(acc0.w, hi);
    unpack_f32x2(o1a, lo, hi); acc1.x = fmaxf(acc1.x, lo); acc1.y = fmaxf(acc1.y, hi);
    unpack_f32x2(o1b, lo, hi); acc1.z = fmaxf(acc1.z, lo); acc1.w = fmaxf(acc1.w, hi);
    unpack_f32x2(o2a, lo, hi); acc2.x = fmaxf(acc2.x, lo); acc2.y = fmaxf(acc2.y, hi);
    unpack_f32x2(o2b, lo, hi); acc2.z = fmaxf(acc2.z, lo); acc2.w = fmaxf(acc2.w, hi);
    unpack_f32x2(o3a, lo, hi); acc3.x = fmaxf(acc3.x, lo); acc3.y = fmaxf(acc3.y, hi);
    unpack_f32x2(o3b, lo, hi); acc3.z = fmaxf(acc3.z, lo); acc3.w = fmaxf(acc3.w, hi);
  }
  const float4 bb = __ldg((const float4*)&b2[chg * 4]);
  const int c0 = chg * 4;
  const int i0 = pt_base + ptg * 4;
  float4 r;
  r.x = fmaxf(acc0.x + bb.x, 0.f); r.y = fmaxf(acc0.y + bb.y, 0.f);
  r.z = fmaxf(acc0.z + bb.z, 0.f); r.w = fmaxf(acc0.w + bb.w, 0.f);
  *(float4*)&out[(i0 + 0) * OD + c0] = r;
  r.x = fmaxf(acc1.x + bb.x, 0.f); r.y = fmaxf(acc1.y + bb.y, 0.f);
  r.z = fmaxf(acc1.z + bb.z, 0.f); r.w = fmaxf(acc1.w + bb.w, 0.f);
  *(float4*)&out[(i0 + 1) * OD + c0] = r;
  r.x = fmaxf(acc2.x + bb.x, 0.f); r.y = fmaxf(acc2.y + bb.y, 0.f);
  r.z = fmaxf(acc2.z + bb.z, 0.f); r.w = fmaxf(acc2.w + bb.w, 0.f);
  *(float4*)&out[(i0 + 2) * OD + c0] = r;
  r.x = fmaxf(acc3.x + bb.x, 0.f); r.y = fmaxf(acc3.y + bb.y, 0.f);
  r.z = fmaxf(acc3.z + bb.z, 0.f); r.w = fmaxf(acc3.w + bb.w, 0.f);
  *(float4*)&out[(i0 + 3) * OD + c0] = r;
}

__global__ void conv1_kernel(const float* __restrict__ W2, const float* __restrict__ b2) {
  conv_impl<32, 64, 32, 128>(g_P1, g_S1, W2, b2, g_x1);
}
__global__ void conv2_kernel(const float* __restrict__ W2, const float* __restrict__ b2) {
  conv_impl<64, 128, 32, 256>(g_P2, g_S2, W2, b2, g_x2);
}

// ---------------- classifier + log_softmax ----------------
#define CLS_WARPS 2
__global__ void classifier_kernel(const float* __restrict__ Wc,
                                  const float* __restrict__ bc,
                                  float* __restrict__ out) {
  __shared__ __align__(16) float xs[CLS_WARPS * 32 * 132];
  __shared__ float wsm[128 * 5];
  __shared__ float bsm[5];
  const int t = threadIdx.x;
  for (int q = t; q < 640; q += 64) wsm[q] = Wc[q];
  if (t < 5) bsm[t] = bc[t];
  const int w = t >> 5, l = t & 31;
  const int base = (blockIdx.x * CLS_WARPS + w) * 32;
  float* xw = &xs[w * 32 * 132];
  for (int r = 0; r < 32; r++) {
    *(float4*)&xw[r * 132 + l * 4] = *(const float4*)&g_x2[(base + r) * 128 + l * 4];
  }
  __syncthreads();
  float a0 = bsm[0], a1 = bsm[1], a2 = bsm[2], a3 = bsm[3], a4 = bsm[4];
  const float* xr = &xw[l * 132];
#pragma unroll 4
  for (int k = 0; k < 128; k++) {
    const float xv = xr[k];
    a0 = fmaf(xv, wsm[k * 5 + 0], a0);
    a1 = fmaf(xv, wsm[k * 5 + 1], a1);
    a2 = fmaf(xv, wsm[k * 5 + 2], a2);
    a3 = fmaf(xv, wsm[k * 5 + 3], a3);
    a4 = fmaf(xv, wsm[k * 5 + 4], a4);
  }
  const float m = fmaxf(fmaxf(fmaxf(a0, a1), fmaxf(a2, a3)), a4);
  const float sum = expf(a0 - m) + expf(a1 - m) + expf(a2 - m) +
                    expf(a3 - m) + expf(a4 - m);
  const float lse = m + logf(sum);
  const int o = (base + l) * 5;
  out[o + 0] = a0 - lse;
  out[o + 1] = a1 - lse;
  out[o + 2] = a2 - lse;
  out[o + 3] = a3 - lse;
  out[o + 4] = a4 - lse;
}

// ---------------- launch (query positioned as 4th launch for ncu capture) ------
extern "C" void kernel_launch(void* const* d_in, const int* in_sizes, int n_in,
                              void* d_out, int out_size) {
  const float* pos = (const float*)d_in[0];
  const float* W1a = (const float*)d_in[1];
  const float* b1a = (const float*)d_in[2];
  const float* W1b = (const float*)d_in[3];
  const float* b1b = (const float*)d_in[4];
  const float* W2a = (const float*)d_in[5];
  const float* b2a = (const float*)d_in[6];
  const float* W2b = (const float*)d_in[7];
  const float* b2b = (const float*)d_in[8];
  const float* Wc  = (const float*)d_in[9];
  const float* bc  = (const float*)d_in[10];
  float* out = (float*)d_out;

  knn_hist_kernel<<<NPTS / 256, 256>>>(pos);       // 1
  knn_scan_kernel<<<1, 1024>>>();                  // 2 (consumes+resets cnt/fill)
  knn_scatter_kernel<<<NPTS / 256, 256>>>(pos);    // 3
  knn_query_kernel<<<NPTS / QPB, QTPB>>>();        // 4  <- profiled launch
  pre1_kernel<<<(NPTS * 32) / 256, 256>>>(pos, W1a, b1a);
  conv1_kernel<<<NPTS / 32, 128>>>(W1b, b1b);
  pre2_kernel<<<(NPTS * 64) / 256, 256>>>(pos, W2a, b2a);
  conv2_kernel<<<NPTS / 32, 256>>>(W2b, b2b);
  classifier_kernel<<<NPTS / (32 * CLS_WARPS), 64>>>(Wc, bc, out);
}

// round 15
// speedup vs baseline: 1.1790x; 1.1790x over previous
#include <cuda_runtime.h>
#include <math.h>

#define NPTS 16384
#define KNN 8
#define GDIM 32
#define NCELL (GDIM * GDIM * GDIM)   // 32768
#define GLO (-5.0f)
#define GSPAN 10.0f
#define LPQ 8             // lanes per query
#define QTPB 256
#define QPB (QTPB / LPQ)  // 32 queries per block

// ---------------- scratch (static device globals; no allocation) ----------------
// NOTE: g_cnt/g_fill start zero (static init) and are re-zeroed by knn_scan_kernel
// after use -> every kernel_launch call sees them zeroed (replay-deterministic).
__device__ __align__(16) float4 g_ppos[NPTS];   // cell-sorted: x,y,z, w=sq
__device__ int   g_pid[NPTS];                   // cell-sorted original ids
__device__ int   g_cellof[NPTS];
__device__ int   g_cnt[NCELL];
__device__ int   g_fill[NCELL];
__device__ int   g_start[NCELL + 1];
__device__ int   g_idx[NPTS * KNN];
__device__ float g_P1[NPTS * 32];
__device__ float g_S1[NPTS * 32];
__device__ float g_x1[NPTS * 64];
__device__ float g_P2[NPTS * 64];
__device__ float g_S2[NPTS * 64];
__device__ float g_x2[NPTS * 128];

typedef unsigned long long u64;

// ---------------- f32x2 packed helpers (sm_100+: fma.rn.f32x2) ----------------
__device__ __forceinline__ u64 splat_f32x2(float v) {
  u64 r;
  asm("mov.b64 %0, {%1, %1};" : "=l"(r) : "f"(v));
  return r;
}
__device__ __forceinline__ u64 fma_f32x2(u64 a, u64 b, u64 c) {
  u64 d;
  asm("fma.rn.f32x2 %0, %1, %2, %3;" : "=l"(d) : "l"(a), "l"(b), "l"(c));
  return d;
}
__device__ __forceinline__ void unpack_f32x2(u64 v, float& lo, float& hi) {
  asm("mov.b64 {%0, %1}, %2;" : "=f"(lo), "=f"(hi) : "l"(v));
}

// Sorted top-8 insertion, static indices only (stays in registers).
__device__ __forceinline__ void insert8(float d, int jj, float bd[KNN], int bi[KNN]) {
#pragma unroll
  for (int s = KNN - 1; s >= 1; s--) {
    bool shift = (d < bd[s - 1]);
    bd[s] = shift ? bd[s - 1] : d;
    bi[s] = shift ? bi[s - 1] : jj;
    if (!shift) return;
  }
  bd[0] = d; bi[0] = jj;
}

__device__ __forceinline__ int cell_coord(float v) {
  const float inv = (float)GDIM / GSPAN;
  int c = (int)floorf((v - GLO) * inv);
  return min(GDIM - 1, max(0, c));
}

// ---------------- grid build ----------------
__global__ void knn_hist_kernel(const float* __restrict__ pos) {
  const int i = blockIdx.x * 256 + threadIdx.x;
  const float x = pos[3 * i], y = pos[3 * i + 1], z = pos[3 * i + 2];
  const int c = (cell_coord(z) * GDIM + cell_coord(y)) * GDIM + cell_coord(x);
  g_cellof[i] = c;
  atomicAdd(&g_cnt[c], 1);
}

// single-block scan over 32768 cells; consumes+resets g_cnt and g_fill
__global__ void __launch_bounds__(1024) knn_scan_kernel() {
  __shared__ int part[1024];
  const int t = threadIdx.x;
  const int base = t * (NCELL / 1024);  // 32 cells per thread
  int loc[NCELL / 1024];
  int s = 0;
#pragma unroll
  for (int k = 0; k < NCELL / 1024; k++) { loc[k] = s; s += g_cnt[base + k]; }
  part[t] = s;
  __syncthreads();
  for (int off = 1; off < 1024; off <<= 1) {
    int v = (t >= off) ? part[t - off] : 0;
    __syncthreads();
    part[t] += v;
    __syncthreads();
  }
  const int excl = part[t] - s;
#pragma unroll
  for (int k = 0; k < NCELL / 1024; k++) {
    g_start[base + k] = excl + loc[k];
    g_cnt[base + k] = 0;    // reset for next replay
    g_fill[base + k] = 0;   // reset for scatter
  }
  if (t == 1023) g_start[NCELL] = NPTS;
}

__global__ void knn_scatter_kernel(const float* __restrict__ pos) {
  const int i = blockIdx.x * 256 + threadIdx.x;
  const int c = g_cellof[i];
  const int slot = g_start[c] + atomicAdd(&g_fill[c], 1);
  const float x = pos[3 * i], y = pos[3 * i + 1], z = pos[3 * i + 2];
  const float sq = fmaf(x, x, fmaf(y, y, z * z));
  g_ppos[slot] = make_float4(x, y, z, sq);
  g_pid[slot] = i;
}

// -------- exact grid kNN: 8 lanes/query, home-row-first certified T-prune,
//          smem merge (round-10 structure; T refreshed only ~2x per query) --------
__global__ void __launch_bounds__(QTPB) knn_query_kernel() {
  const int t = threadIdx.x;
  const int l8 = t & (LPQ - 1);
  const int g = t >> 3;
  const int s = blockIdx.x * QPB + g;           // sorted slot of this query
  const int wl = t & 31;
  const unsigned gmask = 0xFFu << (wl & ~7);    // the 8 lanes of my group

  const float4 me = g_ppos[s];
  const float sqi = me.w;
  const int cx = cell_coord(me.x);
  const int cy = cell_coord(me.y);
  const int cz = cell_coord(me.z);

  float bd[KNN]; int bi[KNN];
#pragma unroll
  for (int k = 0; k < KNN; k++) { bd[k] = 3.0e38f; bi[k] = -1; }
  float worst = 3.0e38f;
  // Certified union-8th upper bound: the 8 lanes' bd[0] are 8 distinct retained
  // elements each <= T, and bd[0] only decreases -> any candidate with d > T is
  // permanently outside the union top-8. Refreshed sparingly (shfl latency).
  float T = 3.0e38f;
  const float h = GSPAN / (float)GDIM;

  // lanes stride a contiguous slot range [lo, hi); prune with stale T
  auto scan_range = [&](int lo, int hi) {
    for (int q = lo + l8; q < hi; q += LPQ) {
      const float4 p = __ldg(&g_ppos[q]);
      const float td = fmaf(me.x, p.x, fmaf(me.y, p.y, me.z * p.z));
      const float d = fmaf(-2.0f, td, sqi + p.w);  // same formula as reference
      if (d <= T && d < worst && q != s) {         // self-exclusion by slot
        insert8(d, q, bd, bi);
        worst = bd[KNN - 1];
      }
    }
  };

  for (int r = 1; r < GDIM; r++) {
    const int x0 = max(cx - r, 0), x1 = min(cx + r, GDIM - 1);
    const int y0 = max(cy - r, 0), y1 = min(cy + r, GDIM - 1);
    const int z0 = max(cz - r, 0), z1 = min(cz + r, GDIM - 1);
    if (r == 1) {
      // home row FIRST (fills all lanes with true near neighbors), then refresh
      // T once, then the remaining 8 rows of the 3x3x3 box with the prune active.
      const int rbh = (cz * GDIM + cy) * GDIM;
      scan_range(__ldg(&g_start[rbh + x0]), __ldg(&g_start[rbh + x1 + 1]));
      {
        float m = bd[0];
        m = fmaxf(m, __shfl_xor_sync(gmask, m, 1, LPQ));
        m = fmaxf(m, __shfl_xor_sync(gmask, m, 2, LPQ));
        m = fmaxf(m, __shfl_xor_sync(gmask, m, 4, LPQ));
        T = m;
      }
      for (int z = z0; z <= z1; z++)
        for (int y = y0; y <= y1; y++) {
          if (z == cz && y == cy) continue;  // home row already done
          const int rb = (z * GDIM + y) * GDIM;
          scan_range(__ldg(&g_start[rb + x0]), __ldg(&g_start[rb + x1 + 1]));
        }
    } else {
      // shell at radius r (box r-1 fully scanned)
      for (int z = z0; z <= z1; z++) {
        const int rz = abs(z - cz);
        for (int y = y0; y <= y1; y++) {
          const int ry = max(rz, abs(y - cy));
          const int rb = (z * GDIM + y) * GDIM;
          if (ry == r) {
            scan_range(__ldg(&g_start[rb + x0]), __ldg(&g_start[rb + x1 + 1]));
          } else {
            if (cx - r >= 0)
              scan_range(__ldg(&g_start[rb + cx - r]), __ldg(&g_start[rb + cx - r + 1]));
            if (cx + r < GDIM)
              scan_range(__ldg(&g_start[rb + cx + r]), __ldg(&g_start[rb + cx + r + 1]));
          }
        }
      }
    }
    // exact min distance from query to unscanned region (clamp-safe):
    // covered/clamped faces contribute 1e18 (so g2<=1e36 < 3e38 sentinel).
    float bnd = 1e18f;
    if (cx - r > 0)         bnd = fminf(bnd, me.x - (GLO + (float)(cx - r) * h));
    if (cx + r < GDIM - 1)  bnd = fminf(bnd, (GLO + (float)(cx + r + 1) * h) - me.x);
    if (cy - r > 0)         bnd = fminf(bnd, me.y - (GLO + (float)(cy - r) * h));
    if (cy + r < GDIM - 1)  bnd = fminf(bnd, (GLO + (float)(cy + r + 1) * h) - me.y);
    if (cz - r > 0)         bnd = fminf(bnd, me.z - (GLO + (float)(cz - r) * h));
    if (cz + r < GDIM - 1)  bnd = fminf(bnd, (GLO + (float)(cz + r + 1) * h) - me.z);
    const float g2 = bnd * bnd;
    int cnt = 0;
#pragma unroll
    for (int k = 0; k < KNN; k++) cnt += (bd[k] < g2) ? 1 : 0;
    cnt += __shfl_xor_sync(gmask, cnt, 1, LPQ);
    cnt += __shfl_xor_sync(gmask, cnt, 2, LPQ);
    cnt += __shfl_xor_sync(gmask, cnt, 4, LPQ);
    // piggyback a T refresh on the ring boundary (helps sparse queries)
    float m = bd[0];
    m = fmaxf(m, __shfl_xor_sync(gmask, m, 1, LPQ));
    m = fmaxf(m, __shfl_xor_sync(gmask, m, 2, LPQ));
    m = fmaxf(m, __shfl_xor_sync(gmask, m, 4, LPQ));
    T = m;
    if (cnt >= KNN) break;  // union's 8th-smallest < g2 <= any unseen point
  }

  // merge 8 sorted lists of 8 via smem, filtered by T (union top-8 all <= T)
  __shared__ float sd[QPB][LPQ * KNN];
  __shared__ int   si[QPB][LPQ * KNN];
#pragma unroll
  for (int k = 0; k < KNN; k++) { sd[g][l8 * KNN + k] = bd[k]; si[g][l8 * KNN + k] = bi[k]; }
  __syncwarp();
  float fd[KNN]; int fi[KNN];
#pragma unroll
  for (int k = 0; k < KNN; k++) { fd[k] = 3.0e38f; fi[k] = -1; }
  for (int k = 0; k < LPQ * KNN; k++) {
    const float d = sd[g][k];
    if (d <= T && d < fd[KNN - 1]) insert8(d, si[g][k], fd, fi);
  }
  const int myid = __ldg(&g_pid[s]);
  g_idx[myid * KNN + l8] = __ldg(&g_pid[fi[l8]]);  // slot -> original id
}

// ---------------- layer-1 factoring: P1[j] = pos_j@(Wtop+Wbot)+b1a, S1[i] = pos_i@Wbot
__global__ void pre1_kernel(const float* __restrict__ pos,
                            const float* __restrict__ W1a,
                            const float* __restrict__ b1a) {
  __shared__ float w[6 * 32];
  __shared__ float b[32];
  if (threadIdx.x < 192) w[threadIdx.x] = W1a[threadIdx.x];
  if (threadIdx.x < 32) b[threadIdx.x] = b1a[threadIdx.x];
  __syncthreads();
  const int t = blockIdx.x * blockDim.x + threadIdx.x;
  const int i = t >> 5, c = t & 31;
  const float x = pos[3 * i], y = pos[3 * i + 1], z = pos[3 * i + 2];
  const float cb = fmaf(x, w[96 + c], fmaf(y, w[128 + c], z * w[160 + c]));
  const float pa = fmaf(x, w[c], fmaf(y, w[32 + c], fmaf(z, w[64 + c], b[c])));
  g_P1[t] = pa + cb;
  g_S1[t] = cb;
}

// ---------------- layer-2 factoring ----------------
__global__ void pre2_kernel(const float* __restrict__ pos,
                            const float* __restrict__ W2a,
                            const float* __restrict__ b2a) {
  const int t = blockIdx.x * blockDim.x + threadIdx.x;
  const int i = t >> 6, c = t & 63;
  float acc = __ldg(&b2a[c]);
  const float* xr = &g_x1[i * 64];
#pragma unroll 8
  for (int k = 0; k < 64; k++) acc = fmaf(xr[k], __ldg(&W2a[k * 64 + c]), acc);
  const float x = pos[3 * i], y = pos[3 * i + 1], z = pos[3 * i + 2];
  const float r = fmaf(x, __ldg(&W2a[64 * 64 + c]),
                  fmaf(y, __ldg(&W2a[65 * 64 + c]), z * __ldg(&W2a[66 * 64 + c])));
  g_P2[t] = acc + r;
  g_S2[t] = r;
}

// ---------------- shared conv core: h = relu(P[j]-S[i]); out = relu(max_s(h@W2) + b2)
// inner GEMM on packed fma.rn.f32x2 (bit-identical per-channel fp32 chains)
template <int HD, int OD, int PTS, int NT>
__device__ __forceinline__ void conv_impl(const float* __restrict__ P,
                                          const float* __restrict__ S,
                                          const float* __restrict__ W2,
                                          const float* __restrict__ b2,
                                          float* __restrict__ out) {
  constexpr int HSTR = PTS + 4;
  constexpr int SSTR = HD + 4;
  constexpr int CHG = OD / 4;
  __shared__ __align__(16) float Hsm[HD * HSTR];
  __shared__ __align__(16) float Ssm[PTS * SSTR];
  __shared__ int Ism[PTS * KNN];
  const int t = threadIdx.x;
  const int pt_base = blockIdx.x * PTS;
  const int chg = t % CHG;
  const int ptg = t / CHG;
  {
    const int lin = t * 8;
    const int p = lin / HD, k = lin % HD;
    const float4 a = *(const float4*)&S[(pt_base + p) * HD + k];
    const float4 bq = *(const float4*)&S[(pt_base + p) * HD + k + 4];
    *(float4*)&Ssm[p * SSTR + k] = a;
    *(float4*)&Ssm[p * SSTR + k + 4] = bq;
  }
  for (int q = t; q < PTS * KNN; q += NT) Ism[q] = g_idx[pt_base * KNN + q];

  float4 acc0 = make_float4(-1e30f, -1e30f, -1e30f, -1e30f);
  float4 acc1 = acc0, acc2 = acc0, acc3 = acc0;

  const int fp = t % PTS;
  const int fk = (t / PTS) * 8;

  for (int s = 0; s <= KNN; s++) {
    __syncthreads();
    {
      const int j = (s < KNN) ? Ism[fp * KNN + s] : (pt_base + fp);
      const float4 a = *(const float4*)&P[j * HD + fk];
      const float4 bq = *(const float4*)&P[j * HD + fk + 4];
      const float4 sa = *(const float4*)&Ssm[fp * SSTR + fk];
      const float4 sb = *(const float4*)&Ssm[fp * SSTR + fk + 4];
      Hsm[(fk + 0) * HSTR + fp] = fmaxf(a.x - sa.x, 0.f);
      Hsm[(fk + 1) * HSTR + fp] = fmaxf(a.y - sa.y, 0.f);
      Hsm[(fk + 2) * HSTR + fp] = fmaxf(a.z - sa.z, 0.f);
      Hsm[(fk + 3) * HSTR + fp] = fmaxf(a.w - sa.w, 0.f);
      Hsm[(fk + 4) * HSTR + fp] = fmaxf(bq.x - sb.x, 0.f);
      Hsm[(fk + 5) * HSTR + fp] = fmaxf(bq.y - sb.y, 0.f);
      Hsm[(fk + 6) * HSTR + fp] = fmaxf(bq.z - sb.z, 0.f);
      Hsm[(fk + 7) * HSTR + fp] = fmaxf(bq.w - sb.w, 0.f);
    }
    __syncthreads();
    u64 o0a = 0, o0b = 0, o1a = 0, o1b = 0, o2a = 0, o2b = 0, o3a = 0, o3b = 0;
#pragma unroll 8
    for (int k = 0; k < HD; k++) {
      const float4 hv = *(const float4*)&Hsm[k * HSTR + ptg * 4];      // broadcast
      const ulonglong2 wv = __ldg((const ulonglong2*)&W2[k * OD + chg * 4]);
      const u64 hx = splat_f32x2(hv.x);
      const u64 hy = splat_f32x2(hv.y);
      const u64 hz = splat_f32x2(hv.z);
      const u64 hw = splat_f32x2(hv.w);
      o0a = fma_f32x2(hx, wv.x, o0a); o0b = fma_f32x2(hx, wv.y, o0b);
      o1a = fma_f32x2(hy, wv.x, o1a); o1b = fma_f32x2(hy, wv.y, o1b);
      o2a = fma_f32x2(hz, wv.x, o2a); o2b = fma_f32x2(hz, wv.y, o2b);
      o3a = fma_f32x2(hw, wv.x, o3a); o3b = fma_f32x2(hw, wv.y, o3b);
    }
    float lo, hi;
    unpack_f32x2(o0a, lo, hi); acc0.x = fmaxf(acc0.x, lo); acc0.y = fmaxf(acc0.y, hi);
    unpack_f32x2(o0b, lo, hi); acc0.z = fmaxf(acc0.z, lo); acc0.w = fmaxf(acc0.w, hi);
    unpack_f32x2(o1a, lo, hi); acc1.x = fmaxf(acc1.x, lo); acc1.y = fmaxf(acc1.y, hi);
    unpack_f32x2(o1b, lo, hi); acc1.z = fmaxf(acc1.z, lo); acc1.w = fmaxf(acc1.w, hi);
    unpack_f32x2(o2a, lo, hi); acc2.x = fmaxf(acc2.x, lo); acc2.y = fmaxf(acc2.y, hi);
    unpack_f32x2(o2b, lo, hi); acc2.z = fmaxf(acc2.z, lo); acc2.w = fmaxf(acc2.w, hi);
    unpack_f32x2(o3a, lo, hi); acc3.x = fmaxf(acc3.x, lo); acc3.y = fmaxf(acc3.y, hi);
    unpack_f32x2(o3b, lo, hi); acc3.z = fmaxf(acc3.z, lo); acc3.w = fmaxf(acc3.w, hi);
  }
  const float4 bb = __ldg((const float4*)&b2[chg * 4]);
  const int c0 = chg * 4;
  const int i0 = pt_base + ptg * 4;
  float4 r;
  r.x = fmaxf(acc0.x + bb.x, 0.f); r.y = fmaxf(acc0.y + bb.y, 0.f);
  r.z = fmaxf(acc0.z + bb.z, 0.f); r.w = fmaxf(acc0.w + bb.w, 0.f);
  *(float4*)&out[(i0 + 0) * OD + c0] = r;
  r.x = fmaxf(acc1.x + bb.x, 0.f); r.y = fmaxf(acc1.y + bb.y, 0.f);
  r.z = fmaxf(acc1.z + bb.z, 0.f); r.w = fmaxf(acc1.w + bb.w, 0.f);
  *(float4*)&out[(i0 + 1) * OD + c0] = r;
  r.x = fmaxf(acc2.x + bb.x, 0.f); r.y = fmaxf(acc2.y + bb.y, 0.f);
  r.z = fmaxf(acc2.z + bb.z, 0.f); r.w = fmaxf(acc2.w + bb.w, 0.f);
  *(float4*)&out[(i0 + 2) * OD + c0] = r;
  r.x = fmaxf(acc3.x + bb.x, 0.f); r.y = fmaxf(acc3.y + bb.y, 0.f);
  r.z = fmaxf(acc3.z + bb.z, 0.f); r.w = fmaxf(acc3.w + bb.w, 0.f);
  *(float4*)&out[(i0 + 3) * OD + c0] = r;
}

__global__ void conv1_kernel(const float* __restrict__ W2, const float* __restrict__ b2) {
  conv_impl<32, 64, 32, 128>(g_P1, g_S1, W2, b2, g_x1);
}
__global__ void conv2_kernel(const float* __restrict__ W2, const float* __restrict__ b2) {
  conv_impl<64, 128, 32, 256>(g_P2, g_S2, W2, b2, g_x2);
}

// ---------------- classifier + log_softmax ----------------
#define CLS_WARPS 2
__global__ void classifier_kernel(const float* __restrict__ Wc,
                                  const float* __restrict__ bc,
                                  float* __restrict__ out) {
  __shared__ __align__(16) float xs[CLS_WARPS * 32 * 132];
  __shared__ float wsm[128 * 5];
  __shared__ float bsm[5];
  const int t = threadIdx.x;
  for (int q = t; q < 640; q += 64) wsm[q] = Wc[q];
  if (t < 5) bsm[t] = bc[t];
  const int w = t >> 5, l = t & 31;
  const int base = (blockIdx.x * CLS_WARPS + w) * 32;
  float* xw = &xs[w * 32 * 132];
  for (int r = 0; r < 32; r++) {
    *(float4*)&xw[r * 132 + l * 4] = *(const float4*)&g_x2[(base + r) * 128 + l * 4];
  }
  __syncthreads();
  float a0 = bsm[0], a1 = bsm[1], a2 = bsm[2], a3 = bsm[3], a4 = bsm[4];
  const float* xr = &xw[l * 132];
#pragma unroll 4
  for (int k = 0; k < 128; k++) {
    const float xv = xr[k];
    a0 = fmaf(xv, wsm[k * 5 + 0], a0);
    a1 = fmaf(xv, wsm[k * 5 + 1], a1);
    a2 = fmaf(xv, wsm[k * 5 + 2], a2);
    a3 = fmaf(xv, wsm[k * 5 + 3], a3);
    a4 = fmaf(xv, wsm[k * 5 + 4], a4);
  }
  const float m = fmaxf(fmaxf(fmaxf(a0, a1), fmaxf(a2, a3)), a4);
  const float sum = expf(a0 - m) + expf(a1 - m) + expf(a2 - m) +
                    expf(a3 - m) + expf(a4 - m);
  const float lse = m + logf(sum);
  const int o = (base + l) * 5;
  out[o + 0] = a0 - lse;
  out[o + 1] = a1 - lse;
  out[o + 2] = a2 - lse;
  out[o + 3] = a3 - lse;
  out[o + 4] = a4 - lse;
}

// ---------------- launch (query positioned as 4th launch for ncu capture) ------
extern "C" void kernel_launch(void* const* d_in, const int* in_sizes, int n_in,
                              void* d_out, int out_size) {
  const float* pos = (const float*)d_in[0];
  const float* W1a = (const float*)d_in[1];
  const float* b1a = (const float*)d_in[2];
  const float* W1b = (const float*)d_in[3];
  const float* b1b = (const float*)d_in[4];
  const float* W2a = (const float*)d_in[5];
  const float* b2a = (const float*)d_in[6];
  const float* W2b = (const float*)d_in[7];
  const float* b2b = (const float*)d_in[8];
  const float* Wc  = (const float*)d_in[9];
  const float* bc  = (const float*)d_in[10];
  float* out = (float*)d_out;

  knn_hist_kernel<<<NPTS / 256, 256>>>(pos);       // 1
  knn_scan_kernel<<<1, 1024>>>();                  // 2 (consumes+resets cnt/fill)
  knn_scatter_kernel<<<NPTS / 256, 256>>>(pos);    // 3
  knn_query_kernel<<<NPTS / QPB, QTPB>>>();        // 4  <- profiled launch
  pre1_kernel<<<(NPTS * 32) / 256, 256>>>(pos, W1a, b1a);
  conv1_kernel<<<NPTS / 32, 128>>>(W1b, b1b);
  pre2_kernel<<<(NPTS * 64) / 256, 256>>>(pos, W2a, b2a);
  conv2_kernel<<<NPTS / 32, 256>>>(W2b, b2b);
  classifier_kernel<<<NPTS / (32 * CLS_WARPS), 64>>>(Wc, bc, out);
}